// round 1
// baseline (speedup 1.0000x reference)
#include <cuda_runtime.h>
#include <cuda_bf16.h>
#include <stdint.h>

#define B_    64
#define H_    6
#define N_    512
#define D_    32
#define NIDX  43          // used bias-table rows: rel_idx in [0,42]
#define KSTR  36          // K smem row stride (bf16 elems), padded for bank-conflict-free B-frag loads
#define VSTR  520         // V^T smem row stride (bf16 elems)

#define SMEM_BYTES ((N_*KSTR*2)*2 + (D_*VSTR*2)*2 + 192)   // 140480 B

__device__ float g_pos[H_ * NIDX];   // bias table, [head][43]

// ---------------------------------------------------------------------------
// Kernel 0: 43-row dynamic position-bias MLP (tiny)
// ---------------------------------------------------------------------------
__device__ __forceinline__ void ln_relu12(const float* x, const float* g, const float* b, float* y) {
    float mu = 0.f;
    #pragma unroll
    for (int j = 0; j < 12; j++) mu += x[j];
    mu *= (1.f / 12.f);
    float var = 0.f;
    #pragma unroll
    for (int j = 0; j < 12; j++) { float d = x[j] - mu; var += d * d; }
    var *= (1.f / 12.f);
    float inv = rsqrtf(var + 1e-5f);
    #pragma unroll
    for (int j = 0; j < 12; j++) {
        float t = (x[j] - mu) * inv * g[j] + b[j];
        y[j] = t > 0.f ? t : 0.f;
    }
}

__global__ void pos_mlp_kernel(
    const float* __restrict__ pw,  const float* __restrict__ pb,
    const float* __restrict__ g1,  const float* __restrict__ b1,
    const float* __restrict__ w1,  const float* __restrict__ bb1,
    const float* __restrict__ g2,  const float* __restrict__ b2,
    const float* __restrict__ w2,  const float* __restrict__ bb2,
    const float* __restrict__ g3,  const float* __restrict__ b3,
    const float* __restrict__ w3,  const float* __restrict__ bb3)
{
    int r = threadIdx.x;
    if (r >= NIDX) return;
    // biases row r (< 43): i0 = 0 -> bh = -7 ; i1 = r/15 ; i2 = r%15
    float c0 = -7.0f;
    float c1 = (float)(r / 15) - 7.0f;
    float c2 = (float)(r % 15) - 7.0f;

    float x[12], y[12];
    #pragma unroll
    for (int j = 0; j < 12; j++)
        x[j] = c0 * pw[j] + c1 * pw[12 + j] + c2 * pw[24 + j] + pb[j];

    ln_relu12(x, g1, b1, y);
    #pragma unroll
    for (int j = 0; j < 12; j++) {
        float s = bb1[j];
        #pragma unroll
        for (int i = 0; i < 12; i++) s += y[i] * w1[i * 12 + j];
        x[j] = s;
    }
    ln_relu12(x, g2, b2, y);
    #pragma unroll
    for (int j = 0; j < 12; j++) {
        float s = bb2[j];
        #pragma unroll
        for (int i = 0; i < 12; i++) s += y[i] * w2[i * 12 + j];
        x[j] = s;
    }
    ln_relu12(x, g3, b3, y);
    #pragma unroll
    for (int h = 0; h < H_; h++) {
        float s = bb3[h];
        #pragma unroll
        for (int i = 0; i < 12; i++) s += y[i] * w3[i * H_ + h];
        g_pos[h * NIDX + r] = s;
    }
}

// ---------------------------------------------------------------------------
// Kernel 1: flash attention, split-bf16 (3x) mma.sync m16n8k16
// ---------------------------------------------------------------------------
__device__ __forceinline__ void mma_bf16(float c[4], const uint32_t a[4], const uint32_t b[2]) {
    asm volatile(
        "mma.sync.aligned.m16n8k16.row.col.f32.bf16.bf16.f32 "
        "{%0,%1,%2,%3}, {%4,%5,%6,%7}, {%8,%9}, {%0,%1,%2,%3};\n"
        : "+f"(c[0]), "+f"(c[1]), "+f"(c[2]), "+f"(c[3])
        : "r"(a[0]), "r"(a[1]), "r"(a[2]), "r"(a[3]), "r"(b[0]), "r"(b[1]));
}

// split x0,x1 into bf16 hi/lo pairs, packed (x0 in low half)
__device__ __forceinline__ void split_pack(float x0, float x1, uint32_t& hi, uint32_t& lo) {
    __nv_bfloat16 h0 = __float2bfloat16(x0);
    __nv_bfloat16 h1 = __float2bfloat16(x1);
    __nv_bfloat16 l0 = __float2bfloat16(x0 - __bfloat162float(h0));
    __nv_bfloat16 l1 = __float2bfloat16(x1 - __bfloat162float(h1));
    hi = ((uint32_t)__bfloat16_as_ushort(h1) << 16) | (uint32_t)__bfloat16_as_ushort(h0);
    lo = ((uint32_t)__bfloat16_as_ushort(l1) << 16) | (uint32_t)__bfloat16_as_ushort(l0);
}

__global__ __launch_bounds__(256, 1) void attn_kernel(
    const float* __restrict__ q, const float* __restrict__ k,
    const float* __restrict__ v, float* __restrict__ out)
{
    extern __shared__ unsigned char smem_raw[];
    __nv_bfloat16* Kh = (__nv_bfloat16*)smem_raw;          // [512][36]
    __nv_bfloat16* Kl = Kh + N_ * KSTR;
    __nv_bfloat16* Vh = Kl + N_ * KSTR;                    // [32][520] (transposed)
    __nv_bfloat16* Vl = Vh + D_ * VSTR;
    float* biasSm = (float*)(Vl + D_ * VSTR);              // [43]

    const int qt = blockIdx.x, head = blockIdx.y, batch = blockIdx.z;
    const size_t bhOff = ((size_t)(batch * H_ + head)) * N_ * D_;
    const float* kb = k + bhOff;
    const float* vb = v + bhOff;
    const float* qb = q + bhOff;
    const int tid = threadIdx.x;

    if (tid < NIDX) biasSm[tid] = g_pos[head * NIDX + tid];

    // --- load K -> split bf16 smem (row-major, padded) ---
    const float4* k4 = (const float4*)kb;
    for (int i = tid; i < N_ * D_ / 4; i += 256) {
        float4 f = k4[i];
        int row = i >> 3, c = (i & 7) << 2;
        float vals[4] = {f.x, f.y, f.z, f.w};
        #pragma unroll
        for (int j = 0; j < 4; j++) {
            __nv_bfloat16 hh = __float2bfloat16(vals[j]);
            Kh[row * KSTR + c + j] = hh;
            Kl[row * KSTR + c + j] = __float2bfloat16(vals[j] - __bfloat162float(hh));
        }
    }
    // --- load V -> split bf16 smem, transposed [dim][kv] ---
    const float4* v4 = (const float4*)vb;
    for (int i = tid; i < N_ * D_ / 4; i += 256) {
        float4 f = v4[i];
        int kv = i >> 3, c = (i & 7) << 2;
        float vals[4] = {f.x, f.y, f.z, f.w};
        #pragma unroll
        for (int j = 0; j < 4; j++) {
            __nv_bfloat16 hh = __float2bfloat16(vals[j]);
            Vh[(c + j) * VSTR + kv] = hh;
            Vl[(c + j) * VSTR + kv] = __float2bfloat16(vals[j] - __bfloat162float(hh));
        }
    }
    __syncthreads();

    const int warp = tid >> 5, lane = tid & 31;
    const int lq = lane >> 2;     // 0..7
    const int le = lane & 3;      // 0..3
    const int e0 = le * 2;
    const int r0 = qt * 128 + warp * 16 + lq;   // global q row in [0,512)
    const int r1 = r0 + 8;
    const int sq0 = (r0 >> 6) + ((r0 >> 3) & 7) + (r0 & 7);
    const int sq1 = (r1 >> 6) + ((r1 >> 3) & 7) + (r1 & 7);

    // --- Q A-fragments (scaled, split) ---
    const float scale = 0.17677669529663687f;  // 32^-0.5
    uint32_t aqh[2][4], aql[2][4];
    #pragma unroll
    for (int ks = 0; ks < 2; ks++) {
        int cb = ks * 16 + e0;
        split_pack(qb[(size_t)r0 * D_ + cb] * scale,     qb[(size_t)r0 * D_ + cb + 1] * scale, aqh[ks][0], aql[ks][0]);
        split_pack(qb[(size_t)r1 * D_ + cb] * scale,     qb[(size_t)r1 * D_ + cb + 1] * scale, aqh[ks][1], aql[ks][1]);
        split_pack(qb[(size_t)r0 * D_ + cb + 8] * scale, qb[(size_t)r0 * D_ + cb + 9] * scale, aqh[ks][2], aql[ks][2]);
        split_pack(qb[(size_t)r1 * D_ + cb + 8] * scale, qb[(size_t)r1 * D_ + cb + 9] * scale, aqh[ks][3], aql[ks][3]);
    }

    float O[4][4];
    #pragma unroll
    for (int d = 0; d < 4; d++)
        #pragma unroll
        for (int j = 0; j < 4; j++) O[d][j] = 0.f;
    float m0 = -1e30f, m1 = -1e30f, l0 = 0.f, l1 = 0.f;

    for (int ch = 0; ch < 8; ch++) {
        // S accumulators init = position bias: bias(q,kcol) = table[s(q)-s(kcol)+21]
        // s(kcol) for kcol = ch*64 + nt*8 + e is exactly ch + nt + e (3-bit fields, no carry)
        float S[8][4];
        #pragma unroll
        for (int nt = 0; nt < 8; nt++) {
            int sk = ch + nt + e0;
            S[nt][0] = biasSm[sq0 - sk + 21];
            S[nt][1] = biasSm[sq0 - sk + 20];
            S[nt][2] = biasSm[sq1 - sk + 21];
            S[nt][3] = biasSm[sq1 - sk + 20];
        }
        // --- S += Q K^T  (3-pass split bf16) ---
        #pragma unroll
        for (int nt = 0; nt < 8; nt++) {
            int n = ch * 64 + nt * 8 + lq;
            #pragma unroll
            for (int ks = 0; ks < 2; ks++) {
                int off = n * KSTR + ks * 16 + e0;
                uint32_t bh[2], bl[2];
                bh[0] = *(const uint32_t*)(Kh + off);
                bh[1] = *(const uint32_t*)(Kh + off + 8);
                bl[0] = *(const uint32_t*)(Kl + off);
                bl[1] = *(const uint32_t*)(Kl + off + 8);
                mma_bf16(S[nt], aqh[ks], bh);
                mma_bf16(S[nt], aqh[ks], bl);
                mma_bf16(S[nt], aql[ks], bh);
            }
        }
        // --- online softmax ---
        float mx0 = -1e30f, mx1 = -1e30f;
        #pragma unroll
        for (int nt = 0; nt < 8; nt++) {
            mx0 = fmaxf(mx0, fmaxf(S[nt][0], S[nt][1]));
            mx1 = fmaxf(mx1, fmaxf(S[nt][2], S[nt][3]));
        }
        mx0 = fmaxf(mx0, __shfl_xor_sync(0xffffffffu, mx0, 1));
        mx0 = fmaxf(mx0, __shfl_xor_sync(0xffffffffu, mx0, 2));
        mx1 = fmaxf(mx1, __shfl_xor_sync(0xffffffffu, mx1, 1));
        mx1 = fmaxf(mx1, __shfl_xor_sync(0xffffffffu, mx1, 2));
        float mn0 = fmaxf(m0, mx0), mn1 = fmaxf(m1, mx1);
        float al0 = __expf(m0 - mn0), al1 = __expf(m1 - mn1);
        m0 = mn0; m1 = mn1;
        l0 *= al0; l1 *= al1;
        #pragma unroll
        for (int d = 0; d < 4; d++) {
            O[d][0] *= al0; O[d][1] *= al0;
            O[d][2] *= al1; O[d][3] *= al1;
        }
        float ps0 = 0.f, ps1 = 0.f;
        #pragma unroll
        for (int nt = 0; nt < 8; nt++) {
            S[nt][0] = __expf(S[nt][0] - mn0); S[nt][1] = __expf(S[nt][1] - mn0);
            S[nt][2] = __expf(S[nt][2] - mn1); S[nt][3] = __expf(S[nt][3] - mn1);
            ps0 += S[nt][0] + S[nt][1];
            ps1 += S[nt][2] + S[nt][3];
        }
        l0 += ps0; l1 += ps1;
        // --- O += P V  (C-frag -> A-frag reuse, 3-pass split bf16) ---
        #pragma unroll
        for (int kk = 0; kk < 4; kk++) {
            uint32_t ah[4], al_[4];
            split_pack(S[2 * kk][0],     S[2 * kk][1],     ah[0], al_[0]);
            split_pack(S[2 * kk][2],     S[2 * kk][3],     ah[1], al_[1]);
            split_pack(S[2 * kk + 1][0], S[2 * kk + 1][1], ah[2], al_[2]);
            split_pack(S[2 * kk + 1][2], S[2 * kk + 1][3], ah[3], al_[3]);
            int kbase = ch * 64 + kk * 16 + e0;
            #pragma unroll
            for (int dt = 0; dt < 4; dt++) {
                int off = (dt * 8 + lq) * VSTR + kbase;
                uint32_t bh[2], bl[2];
                bh[0] = *(const uint32_t*)(Vh + off);
                bh[1] = *(const uint32_t*)(Vh + off + 8);
                bl[0] = *(const uint32_t*)(Vl + off);
                bl[1] = *(const uint32_t*)(Vl + off + 8);
                mma_bf16(O[dt], ah,  bh);
                mma_bf16(O[dt], ah,  bl);
                mma_bf16(O[dt], al_, bh);
            }
        }
    }

    // --- finalize: reduce l across the 4-lane row group, normalize, store ---
    l0 += __shfl_xor_sync(0xffffffffu, l0, 1);
    l0 += __shfl_xor_sync(0xffffffffu, l0, 2);
    l1 += __shfl_xor_sync(0xffffffffu, l1, 1);
    l1 += __shfl_xor_sync(0xffffffffu, l1, 2);
    float i0 = 1.f / l0, i1 = 1.f / l1;
    float* ob = out + bhOff;
    #pragma unroll
    for (int dt = 0; dt < 4; dt++) {
        int c = dt * 8 + e0;
        float2 o01; o01.x = O[dt][0] * i0; o01.y = O[dt][1] * i0;
        float2 o23; o23.x = O[dt][2] * i1; o23.y = O[dt][3] * i1;
        *(float2*)(ob + (size_t)r0 * D_ + c) = o01;
        *(float2*)(ob + (size_t)r1 * D_ + c) = o23;
    }
}

// ---------------------------------------------------------------------------
extern "C" void kernel_launch(void* const* d_in, const int* in_sizes, int n_in,
                              void* d_out, int out_size)
{
    const float* q = (const float*)d_in[0];
    const float* k = (const float*)d_in[1];
    const float* v = (const float*)d_in[2];
    // inputs h,w,d may or may not appear as scalar tensors; detect via size of
    // the first MLP param (pos_proj_w has 36 elements, the scalars have 1).
    int base = (in_sizes[3] == 36) ? 3 : 6;
    const float* pw  = (const float*)d_in[base + 0];
    const float* pb  = (const float*)d_in[base + 1];
    const float* g1  = (const float*)d_in[base + 2];
    const float* b1  = (const float*)d_in[base + 3];
    const float* w1  = (const float*)d_in[base + 4];
    const float* bb1 = (const float*)d_in[base + 5];
    const float* g2  = (const float*)d_in[base + 6];
    const float* b2  = (const float*)d_in[base + 7];
    const float* w2  = (const float*)d_in[base + 8];
    const float* bb2 = (const float*)d_in[base + 9];
    const float* g3  = (const float*)d_in[base + 10];
    const float* b3  = (const float*)d_in[base + 11];
    const float* w3  = (const float*)d_in[base + 12];
    const float* bb3 = (const float*)d_in[base + 13];
    float* out = (float*)d_out;

    cudaFuncSetAttribute(attn_kernel, cudaFuncAttributeMaxDynamicSharedMemorySize, SMEM_BYTES);

    pos_mlp_kernel<<<1, 64>>>(pw, pb, g1, b1, w1, bb1, g2, b2, w2, bb2, g3, b3, w3, bb3);

    dim3 grid(N_ / 128, H_, B_);
    attn_kernel<<<grid, 256, SMEM_BYTES>>>(q, k, v, out);
}

// round 2
// speedup vs baseline: 1.6426x; 1.6426x over previous
#include <cuda_runtime.h>
#include <cuda_bf16.h>
#include <stdint.h>

#define B_    64
#define H_    6
#define N_    512
#define D_    32
#define NIDX  43          // used bias-table rows: rel_idx in [0,42]
#define CH_   256         // KV chunk rows held in smem at once
#define KSTR  36          // K smem row stride (bf16 elems)
#define VSTR  264         // V^T smem row stride (bf16 elems), CH_+8 pad

// per-CTA smem: K split + V split + bias
#define SMEM_BYTES ((CH_*KSTR*2)*2 + (D_*VSTR*2)*2 + 192)   // ~70.9 KB -> 2 CTAs/SM

__device__ float g_pos[H_ * NIDX];   // bias table, [head][43]

// ---------------------------------------------------------------------------
// Kernel 0: 43-row dynamic position-bias MLP (tiny)
// ---------------------------------------------------------------------------
__device__ __forceinline__ void ln_relu12(const float* x, const float* g, const float* b, float* y) {
    float mu = 0.f;
    #pragma unroll
    for (int j = 0; j < 12; j++) mu += x[j];
    mu *= (1.f / 12.f);
    float var = 0.f;
    #pragma unroll
    for (int j = 0; j < 12; j++) { float d = x[j] - mu; var += d * d; }
    var *= (1.f / 12.f);
    float inv = rsqrtf(var + 1e-5f);
    #pragma unroll
    for (int j = 0; j < 12; j++) {
        float t = (x[j] - mu) * inv * g[j] + b[j];
        y[j] = t > 0.f ? t : 0.f;
    }
}

__global__ void pos_mlp_kernel(
    const float* __restrict__ pw,  const float* __restrict__ pb,
    const float* __restrict__ g1,  const float* __restrict__ b1,
    const float* __restrict__ w1,  const float* __restrict__ bb1,
    const float* __restrict__ g2,  const float* __restrict__ b2,
    const float* __restrict__ w2,  const float* __restrict__ bb2,
    const float* __restrict__ g3,  const float* __restrict__ b3,
    const float* __restrict__ w3,  const float* __restrict__ bb3)
{
    int r = threadIdx.x;
    if (r >= NIDX) return;
    float c0 = -7.0f;
    float c1 = (float)(r / 15) - 7.0f;
    float c2 = (float)(r % 15) - 7.0f;

    float x[12], y[12];
    #pragma unroll
    for (int j = 0; j < 12; j++)
        x[j] = c0 * pw[j] + c1 * pw[12 + j] + c2 * pw[24 + j] + pb[j];

    ln_relu12(x, g1, b1, y);
    #pragma unroll
    for (int j = 0; j < 12; j++) {
        float s = bb1[j];
        #pragma unroll
        for (int i = 0; i < 12; i++) s += y[i] * w1[i * 12 + j];
        x[j] = s;
    }
    ln_relu12(x, g2, b2, y);
    #pragma unroll
    for (int j = 0; j < 12; j++) {
        float s = bb2[j];
        #pragma unroll
        for (int i = 0; i < 12; i++) s += y[i] * w2[i * 12 + j];
        x[j] = s;
    }
    ln_relu12(x, g3, b3, y);
    #pragma unroll
    for (int h = 0; h < H_; h++) {
        float s = bb3[h];
        #pragma unroll
        for (int i = 0; i < 12; i++) s += y[i] * w3[i * H_ + h];
        g_pos[h * NIDX + r] = s;
    }
}

// ---------------------------------------------------------------------------
// Kernel 1: flash attention, split-bf16 (3x) mma.sync m16n8k16, chunked KV
// ---------------------------------------------------------------------------
__device__ __forceinline__ void mma_bf16(float c[4], const uint32_t a[4], const uint32_t b[2]) {
    asm volatile(
        "mma.sync.aligned.m16n8k16.row.col.f32.bf16.bf16.f32 "
        "{%0,%1,%2,%3}, {%4,%5,%6,%7}, {%8,%9}, {%0,%1,%2,%3};\n"
        : "+f"(c[0]), "+f"(c[1]), "+f"(c[2]), "+f"(c[3])
        : "r"(a[0]), "r"(a[1]), "r"(a[2]), "r"(a[3]), "r"(b[0]), "r"(b[1]));
}

__device__ __forceinline__ void split_pack(float x0, float x1, uint32_t& hi, uint32_t& lo) {
    __nv_bfloat16 h0 = __float2bfloat16(x0);
    __nv_bfloat16 h1 = __float2bfloat16(x1);
    __nv_bfloat16 l0 = __float2bfloat16(x0 - __bfloat162float(h0));
    __nv_bfloat16 l1 = __float2bfloat16(x1 - __bfloat162float(h1));
    hi = ((uint32_t)__bfloat16_as_ushort(h1) << 16) | (uint32_t)__bfloat16_as_ushort(h0);
    lo = ((uint32_t)__bfloat16_as_ushort(l1) << 16) | (uint32_t)__bfloat16_as_ushort(l0);
}

__global__ __launch_bounds__(256, 2) void attn_kernel(
    const float* __restrict__ q, const float* __restrict__ k,
    const float* __restrict__ v, float* __restrict__ out)
{
    extern __shared__ unsigned char smem_raw[];
    __nv_bfloat16* Kh = (__nv_bfloat16*)smem_raw;          // [256][36]
    __nv_bfloat16* Kl = Kh + CH_ * KSTR;
    __nv_bfloat16* Vh = Kl + CH_ * KSTR;                   // [32][264] (transposed)
    __nv_bfloat16* Vl = Vh + D_ * VSTR;
    float* biasSm = (float*)(Vl + D_ * VSTR);              // [43]

    const int qt = blockIdx.x, head = blockIdx.y, batch = blockIdx.z;
    const size_t bhOff = ((size_t)(batch * H_ + head)) * N_ * D_;
    const float* kb = k + bhOff;
    const float* vb = v + bhOff;
    const float* qb = q + bhOff;
    const int tid = threadIdx.x;

    if (tid < NIDX) biasSm[tid] = g_pos[head * NIDX + tid];

    const int warp = tid >> 5, lane = tid & 31;
    const int lq = lane >> 2;     // 0..7
    const int le = lane & 3;      // 0..3
    const int e0 = le * 2;
    const int r0 = qt * 128 + warp * 16 + lq;   // global q row in [0,512)
    const int r1 = r0 + 8;
    const int sq0 = (r0 >> 6) + ((r0 >> 3) & 7) + (r0 & 7);
    const int sq1 = (r1 >> 6) + ((r1 >> 3) & 7) + (r1 & 7);

    // --- Q A-fragments (scaled, split); issued before smem fill to overlap ---
    const float scale = 0.17677669529663687f;  // 32^-0.5
    uint32_t aqh[2][4], aql[2][4];
    #pragma unroll
    for (int ks = 0; ks < 2; ks++) {
        int cb = ks * 16 + e0;
        split_pack(qb[(size_t)r0 * D_ + cb] * scale,     qb[(size_t)r0 * D_ + cb + 1] * scale, aqh[ks][0], aql[ks][0]);
        split_pack(qb[(size_t)r1 * D_ + cb] * scale,     qb[(size_t)r1 * D_ + cb + 1] * scale, aqh[ks][1], aql[ks][1]);
        split_pack(qb[(size_t)r0 * D_ + cb + 8] * scale, qb[(size_t)r0 * D_ + cb + 9] * scale, aqh[ks][2], aql[ks][2]);
        split_pack(qb[(size_t)r1 * D_ + cb + 8] * scale, qb[(size_t)r1 * D_ + cb + 9] * scale, aqh[ks][3], aql[ks][3]);
    }

    float O[4][4];
    #pragma unroll
    for (int d = 0; d < 4; d++)
        #pragma unroll
        for (int j = 0; j < 4; j++) O[d][j] = 0.f;
    float m0 = -1e30f, m1 = -1e30f, l0 = 0.f, l1 = 0.f;

    for (int ch2 = 0; ch2 < 2; ch2++) {
        if (ch2) __syncthreads();   // protect smem from overwrite while in use

        // --- load K chunk -> split bf16 smem (row-major, padded) ---
        const float4* k4 = (const float4*)(kb + (size_t)ch2 * CH_ * D_);
        for (int i = tid; i < CH_ * D_ / 4; i += 256) {
            float4 f = k4[i];
            int row = i >> 3, c = (i & 7) << 2;
            float vals[4] = {f.x, f.y, f.z, f.w};
            #pragma unroll
            for (int j = 0; j < 4; j++) {
                __nv_bfloat16 hh = __float2bfloat16(vals[j]);
                Kh[row * KSTR + c + j] = hh;
                Kl[row * KSTR + c + j] = __float2bfloat16(vals[j] - __bfloat162float(hh));
            }
        }
        // --- load V chunk -> split bf16 smem, transposed [dim][kv_local] ---
        const float4* v4 = (const float4*)(vb + (size_t)ch2 * CH_ * D_);
        for (int i = tid; i < CH_ * D_ / 4; i += 256) {
            float4 f = v4[i];
            int kv = i >> 3, c = (i & 7) << 2;
            float vals[4] = {f.x, f.y, f.z, f.w};
            #pragma unroll
            for (int j = 0; j < 4; j++) {
                __nv_bfloat16 hh = __float2bfloat16(vals[j]);
                Vh[(c + j) * VSTR + kv] = hh;
                Vl[(c + j) * VSTR + kv] = __float2bfloat16(vals[j] - __bfloat162float(hh));
            }
        }
        __syncthreads();

        for (int c4 = 0; c4 < 4; c4++) {
            const int ch = ch2 * 4 + c4;     // global 64-row block index
            // S accumulators init = position bias: bias(q,kcol)=table[s(q)-s(kcol)+21]
            float S[8][4];
            #pragma unroll
            for (int nt = 0; nt < 8; nt++) {
                int sk = ch + nt + e0;
                S[nt][0] = biasSm[sq0 - sk + 21];
                S[nt][1] = biasSm[sq0 - sk + 20];
                S[nt][2] = biasSm[sq1 - sk + 21];
                S[nt][3] = biasSm[sq1 - sk + 20];
            }
            // --- S += Q K^T  (3-pass split bf16) ---
            #pragma unroll
            for (int nt = 0; nt < 8; nt++) {
                int n = c4 * 64 + nt * 8 + lq;   // row within chunk
                #pragma unroll
                for (int ks = 0; ks < 2; ks++) {
                    int off = n * KSTR + ks * 16 + e0;
                    uint32_t bh[2], bl[2];
                    bh[0] = *(const uint32_t*)(Kh + off);
                    bh[1] = *(const uint32_t*)(Kh + off + 8);
                    bl[0] = *(const uint32_t*)(Kl + off);
                    bl[1] = *(const uint32_t*)(Kl + off + 8);
                    mma_bf16(S[nt], aqh[ks], bh);
                    mma_bf16(S[nt], aqh[ks], bl);
                    mma_bf16(S[nt], aql[ks], bh);
                }
            }
            // --- online softmax ---
            float mx0 = -1e30f, mx1 = -1e30f;
            #pragma unroll
            for (int nt = 0; nt < 8; nt++) {
                mx0 = fmaxf(mx0, fmaxf(S[nt][0], S[nt][1]));
                mx1 = fmaxf(mx1, fmaxf(S[nt][2], S[nt][3]));
            }
            mx0 = fmaxf(mx0, __shfl_xor_sync(0xffffffffu, mx0, 1));
            mx0 = fmaxf(mx0, __shfl_xor_sync(0xffffffffu, mx0, 2));
            mx1 = fmaxf(mx1, __shfl_xor_sync(0xffffffffu, mx1, 1));
            mx1 = fmaxf(mx1, __shfl_xor_sync(0xffffffffu, mx1, 2));
            float mn0 = fmaxf(m0, mx0), mn1 = fmaxf(m1, mx1);
            float al0 = __expf(m0 - mn0), al1 = __expf(m1 - mn1);
            m0 = mn0; m1 = mn1;
            l0 *= al0; l1 *= al1;
            #pragma unroll
            for (int d = 0; d < 4; d++) {
                O[d][0] *= al0; O[d][1] *= al0;
                O[d][2] *= al1; O[d][3] *= al1;
            }
            float ps0 = 0.f, ps1 = 0.f;
            #pragma unroll
            for (int nt = 0; nt < 8; nt++) {
                S[nt][0] = __expf(S[nt][0] - mn0); S[nt][1] = __expf(S[nt][1] - mn0);
                S[nt][2] = __expf(S[nt][2] - mn1); S[nt][3] = __expf(S[nt][3] - mn1);
                ps0 += S[nt][0] + S[nt][1];
                ps1 += S[nt][2] + S[nt][3];
            }
            l0 += ps0; l1 += ps1;
            // --- O += P V  (C-frag -> A-frag reuse, 3-pass split bf16) ---
            #pragma unroll
            for (int kk = 0; kk < 4; kk++) {
                uint32_t ah[4], al_[4];
                split_pack(S[2 * kk][0],     S[2 * kk][1],     ah[0], al_[0]);
                split_pack(S[2 * kk][2],     S[2 * kk][3],     ah[1], al_[1]);
                split_pack(S[2 * kk + 1][0], S[2 * kk + 1][1], ah[2], al_[2]);
                split_pack(S[2 * kk + 1][2], S[2 * kk + 1][3], ah[3], al_[3]);
                int kbase = c4 * 64 + kk * 16 + e0;   // col within chunk
                #pragma unroll
                for (int dt = 0; dt < 4; dt++) {
                    int off = (dt * 8 + lq) * VSTR + kbase;
                    uint32_t bh[2], bl[2];
                    bh[0] = *(const uint32_t*)(Vh + off);
                    bh[1] = *(const uint32_t*)(Vh + off + 8);
                    bl[0] = *(const uint32_t*)(Vl + off);
                    bl[1] = *(const uint32_t*)(Vl + off + 8);
                    mma_bf16(O[dt], ah,  bh);
                    mma_bf16(O[dt], ah,  bl);
                    mma_bf16(O[dt], al_, bh);
                }
            }
        }
    }

    // --- finalize: reduce l across the 4-lane row group, normalize, store ---
    l0 += __shfl_xor_sync(0xffffffffu, l0, 1);
    l0 += __shfl_xor_sync(0xffffffffu, l0, 2);
    l1 += __shfl_xor_sync(0xffffffffu, l1, 1);
    l1 += __shfl_xor_sync(0xffffffffu, l1, 2);
    float i0 = 1.f / l0, i1 = 1.f / l1;
    float* ob = out + bhOff;
    #pragma unroll
    for (int dt = 0; dt < 4; dt++) {
        int c = dt * 8 + e0;
        float2 o01; o01.x = O[dt][0] * i0; o01.y = O[dt][1] * i0;
        float2 o23; o23.x = O[dt][2] * i1; o23.y = O[dt][3] * i1;
        *(float2*)(ob + (size_t)r0 * D_ + c) = o01;
        *(float2*)(ob + (size_t)r1 * D_ + c) = o23;
    }
}

// ---------------------------------------------------------------------------
extern "C" void kernel_launch(void* const* d_in, const int* in_sizes, int n_in,
                              void* d_out, int out_size)
{
    const float* q = (const float*)d_in[0];
    const float* k = (const float*)d_in[1];
    const float* v = (const float*)d_in[2];
    int base = (in_sizes[3] == 36) ? 3 : 6;
    const float* pw  = (const float*)d_in[base + 0];
    const float* pb  = (const float*)d_in[base + 1];
    const float* g1  = (const float*)d_in[base + 2];
    const float* b1  = (const float*)d_in[base + 3];
    const float* w1  = (const float*)d_in[base + 4];
    const float* bb1 = (const float*)d_in[base + 5];
    const float* g2  = (const float*)d_in[base + 6];
    const float* b2  = (const float*)d_in[base + 7];
    const float* w2  = (const float*)d_in[base + 8];
    const float* bb2 = (const float*)d_in[base + 9];
    const float* g3  = (const float*)d_in[base + 10];
    const float* b3  = (const float*)d_in[base + 11];
    const float* w3  = (const float*)d_in[base + 12];
    const float* bb3 = (const float*)d_in[base + 13];
    float* out = (float*)d_out;

    cudaFuncSetAttribute(attn_kernel, cudaFuncAttributeMaxDynamicSharedMemorySize, SMEM_BYTES);

    pos_mlp_kernel<<<1, 64>>>(pw, pb, g1, b1, w1, bb1, g2, b2, w2, bb2, g3, b3, w3, bb3);

    dim3 grid(N_ / 128, H_, B_);
    attn_kernel<<<grid, 256, SMEM_BYTES>>>(q, k, v, out);
}

// round 3
// speedup vs baseline: 1.7434x; 1.0614x over previous
#include <cuda_runtime.h>
#include <cuda_bf16.h>
#include <stdint.h>

#define B_    64
#define H_    6
#define N_    512
#define D_    32
#define NIDX  43           // used bias-table rows
#define BH_   (B_*H_)      // 384
#define CH_   128          // KV rows per chunk
#define NCH   4            // chunks
#define LOG2E 1.4426950408889634f

// smem layout (16B units):
//   Kbuf: 2 bufs x 128 rows x 12 units (8 used + 4 pad -> 192B row stride)
//   Vbuf: 2 bufs x 32 rows x 36 units (32 used + 4 pad -> 576B row stride)
#define KROW_U   12
#define KBUF_U   (CH_*KROW_U)          // 1536
#define VROW_U   36
#define VBUF_U   (D_*VROW_U)           // 1152
#define SMEM_U   (2*KBUF_U + 2*VBUF_U) // 5376 units
#define SMEM_BYTES (SMEM_U*16 + 192)   // ~86.2 KB -> 2 CTAs/SM

// pre-split K/V in gmem, layout mirrors smem (dense, 8 / 32 units per row)
__device__ uint4 g_Ksplit[BH_ * NCH * CH_ * 8];   // 25.2 MB
__device__ uint4 g_Vsplit[BH_ * NCH * D_ * 32];   // 25.2 MB
__device__ float g_pos[H_ * NIDX];

// ---------------------------------------------------------------------------
// helpers
// ---------------------------------------------------------------------------
__device__ __forceinline__ void split2(float x0, float x1, uint32_t& hi, uint32_t& lo) {
    uint32_t h;
    asm("cvt.rn.bf16x2.f32 %0, %1, %2;" : "=r"(h) : "f"(x1), "f"(x0));
    float h0 = __uint_as_float(h << 16);
    float h1 = __uint_as_float(h & 0xffff0000u);
    asm("cvt.rn.bf16x2.f32 %0, %1, %2;" : "=r"(lo) : "f"(x1 - h1), "f"(x0 - h0));
    hi = h;
}

__device__ __forceinline__ float ex2(float x) {
    float y; asm("ex2.approx.f32 %0, %1;" : "=f"(y) : "f"(x)); return y;
}

__device__ __forceinline__ void mma_bf16(float c[4], const uint32_t a[4], const uint32_t b[2]) {
    asm volatile(
        "mma.sync.aligned.m16n8k16.row.col.f32.bf16.bf16.f32 "
        "{%0,%1,%2,%3}, {%4,%5,%6,%7}, {%8,%9}, {%0,%1,%2,%3};\n"
        : "+f"(c[0]), "+f"(c[1]), "+f"(c[2]), "+f"(c[3])
        : "r"(a[0]), "r"(a[1]), "r"(a[2]), "r"(a[3]), "r"(b[0]), "r"(b[1]));
}

__device__ __forceinline__ void cp16(uint32_t dst, const void* src) {
    asm volatile("cp.async.cg.shared.global [%0], [%1], 16;" :: "r"(dst), "l"(src));
}

// ---------------------------------------------------------------------------
// Kernel 0: 43-row dynamic position-bias MLP
// ---------------------------------------------------------------------------
__device__ __forceinline__ void ln_relu12(const float* x, const float* g, const float* b, float* y) {
    float mu = 0.f;
    #pragma unroll
    for (int j = 0; j < 12; j++) mu += x[j];
    mu *= (1.f / 12.f);
    float var = 0.f;
    #pragma unroll
    for (int j = 0; j < 12; j++) { float d = x[j] - mu; var += d * d; }
    var *= (1.f / 12.f);
    float inv = rsqrtf(var + 1e-5f);
    #pragma unroll
    for (int j = 0; j < 12; j++) {
        float t = (x[j] - mu) * inv * g[j] + b[j];
        y[j] = t > 0.f ? t : 0.f;
    }
}

__global__ void pos_mlp_kernel(
    const float* __restrict__ pw,  const float* __restrict__ pb,
    const float* __restrict__ g1,  const float* __restrict__ b1,
    const float* __restrict__ w1,  const float* __restrict__ bb1,
    const float* __restrict__ g2,  const float* __restrict__ b2,
    const float* __restrict__ w2,  const float* __restrict__ bb2,
    const float* __restrict__ g3,  const float* __restrict__ b3,
    const float* __restrict__ w3,  const float* __restrict__ bb3)
{
    int r = threadIdx.x;
    if (r >= NIDX) return;
    float c0 = -7.0f;
    float c1 = (float)(r / 15) - 7.0f;
    float c2 = (float)(r % 15) - 7.0f;

    float x[12], y[12];
    #pragma unroll
    for (int j = 0; j < 12; j++)
        x[j] = c0 * pw[j] + c1 * pw[12 + j] + c2 * pw[24 + j] + pb[j];

    ln_relu12(x, g1, b1, y);
    #pragma unroll
    for (int j = 0; j < 12; j++) {
        float s = bb1[j];
        #pragma unroll
        for (int i = 0; i < 12; i++) s += y[i] * w1[i * 12 + j];
        x[j] = s;
    }
    ln_relu12(x, g2, b2, y);
    #pragma unroll
    for (int j = 0; j < 12; j++) {
        float s = bb2[j];
        #pragma unroll
        for (int i = 0; i < 12; i++) s += y[i] * w2[i * 12 + j];
        x[j] = s;
    }
    ln_relu12(x, g3, b3, y);
    #pragma unroll
    for (int h = 0; h < H_; h++) {
        float s = bb3[h];
        #pragma unroll
        for (int i = 0; i < 12; i++) s += y[i] * w3[i * H_ + h];
        g_pos[h * NIDX + r] = s;
    }
}

// ---------------------------------------------------------------------------
// Kernel 1: pre-split K/V into interleaved (hi0,hi1,lo0,lo1) 16B words
// ---------------------------------------------------------------------------
__global__ __launch_bounds__(256) void split_kv_kernel(
    const float* __restrict__ k, const float* __restrict__ v)
{
    __shared__ float vs[CH_ * 33];
    const int bh = blockIdx.x;
    const int tid = threadIdx.x;
    const float* kb = k + (size_t)bh * N_ * D_;
    const float* vb = v + (size_t)bh * N_ * D_;

    for (int ch = 0; ch < NCH; ch++) {
        // K: direct from gmem rows (row-major, contiguous)
        for (int i = tid; i < CH_ * 8; i += 256) {
            int n2 = i >> 3, u = i & 7;
            int ks = u >> 2, le = u & 3;
            const float* row = kb + (size_t)(ch * CH_ + n2) * D_;
            int c0 = ks * 16 + le * 2;
            float a0 = row[c0], a1 = row[c0 + 1], a2 = row[c0 + 8], a3 = row[c0 + 9];
            uint4 w;
            split2(a0, a1, w.x, w.z);
            split2(a2, a3, w.y, w.w);
            g_Ksplit[(size_t)(bh * NCH + ch) * (CH_ * 8) + i] = w;
        }
        // V: stage chunk in smem (coalesced), then transpose-gather
        __syncthreads();
        for (int i = tid; i < CH_ * D_; i += 256) {
            int kv = i >> 5, d = i & 31;
            vs[kv * 33 + d] = vb[(size_t)(ch * CH_) * D_ + i];
        }
        __syncthreads();
        for (int i = tid; i < D_ * 32; i += 256) {
            int d = i >> 5, w_ = i & 31;
            int kkloc = w_ >> 2, le = w_ & 3;
            int kv0 = kkloc * 16 + le * 2;
            float a0 = vs[kv0 * 33 + d];
            float a1 = vs[(kv0 + 1) * 33 + d];
            float a2 = vs[(kv0 + 8) * 33 + d];
            float a3 = vs[(kv0 + 9) * 33 + d];
            uint4 w;
            split2(a0, a1, w.x, w.z);
            split2(a2, a3, w.y, w.w);
            g_Vsplit[(size_t)(bh * NCH + ch) * (D_ * 32) + i] = w;
        }
        __syncthreads();
    }
}

// ---------------------------------------------------------------------------
// Kernel 2: flash attention, split-bf16 3-pass MMA, cp.async pipelined chunks
// ---------------------------------------------------------------------------
__global__ __launch_bounds__(256, 2) void attn_kernel(
    const float* __restrict__ q, float* __restrict__ out)
{
    extern __shared__ uint4 smem4[];
    float* biasSm = (float*)(smem4 + SMEM_U);

    const int qt = blockIdx.x, head = blockIdx.y, batch = blockIdx.z;
    const int bh = batch * H_ + head;
    const size_t bhOff = (size_t)bh * N_ * D_;
    const float* qb = q + bhOff;
    const int tid = threadIdx.x;

    uint32_t smem_u32;
    asm("{ .reg .u64 t; cvta.to.shared.u64 t, %1; cvt.u32.u64 %0, t; }"
        : "=r"(smem_u32) : "l"(smem4));

    if (tid < NIDX) biasSm[tid] = g_pos[head * NIDX + tid] * LOG2E;

    const int warp = tid >> 5, lane = tid & 31;
    const int lq = lane >> 2;
    const int le = lane & 3;
    const int e0 = le * 2;
    const int r0 = qt * 128 + warp * 16 + lq;
    const int r1 = r0 + 8;
    const int sq0 = (r0 >> 6) + ((r0 >> 3) & 7) + (r0 & 7);
    const int sq1 = (r1 >> 6) + ((r1 >> 3) & 7) + (r1 & 7);

    // --- fill chunk 0 (cp.async) ---
    const int bh4 = bh * NCH;
    {
        const uint4* gk = g_Ksplit + (size_t)bh4 * (CH_ * 8);
        uint32_t kd = smem_u32;
        for (int i = tid; i < CH_ * 8; i += 256) {
            int n2 = i >> 3, u = i & 7;
            cp16(kd + (n2 * KROW_U + u) * 16, gk + i);
        }
        const uint4* gv = g_Vsplit + (size_t)bh4 * (D_ * 32);
        uint32_t vd = smem_u32 + 2 * KBUF_U * 16;
        for (int i = tid; i < D_ * 32; i += 256) {
            int d = i >> 5, w_ = i & 31;
            cp16(vd + (d * VROW_U + w_) * 16, gv + i);
        }
        asm volatile("cp.async.commit_group;" ::: "memory");
    }

    // --- Q A-fragments (scaled into log2 domain, split) ---
    const float scale = 0.17677669529663687f * LOG2E;
    uint32_t aqh[2][4], aql[2][4];
    #pragma unroll
    for (int ks = 0; ks < 2; ks++) {
        int cb = ks * 16 + e0;
        split2(qb[(size_t)r0 * D_ + cb] * scale,     qb[(size_t)r0 * D_ + cb + 1] * scale, aqh[ks][0], aql[ks][0]);
        split2(qb[(size_t)r1 * D_ + cb] * scale,     qb[(size_t)r1 * D_ + cb + 1] * scale, aqh[ks][1], aql[ks][1]);
        split2(qb[(size_t)r0 * D_ + cb + 8] * scale, qb[(size_t)r0 * D_ + cb + 9] * scale, aqh[ks][2], aql[ks][2]);
        split2(qb[(size_t)r1 * D_ + cb + 8] * scale, qb[(size_t)r1 * D_ + cb + 9] * scale, aqh[ks][3], aql[ks][3]);
    }

    float O[4][4];
    #pragma unroll
    for (int d = 0; d < 4; d++)
        #pragma unroll
        for (int j = 0; j < 4; j++) O[d][j] = 0.f;
    float m0 = -1e30f, m1 = -1e30f, l0 = 0.f, l1 = 0.f;

    for (int ch = 0; ch < NCH; ch++) {
        // prefetch next chunk into the other buffer
        if (ch + 1 < NCH) {
            int b = (ch + 1) & 1;
            const uint4* gk = g_Ksplit + (size_t)(bh4 + ch + 1) * (CH_ * 8);
            uint32_t kd = smem_u32 + b * KBUF_U * 16;
            for (int i = tid; i < CH_ * 8; i += 256) {
                int n2 = i >> 3, u = i & 7;
                cp16(kd + (n2 * KROW_U + u) * 16, gk + i);
            }
            const uint4* gv = g_Vsplit + (size_t)(bh4 + ch + 1) * (D_ * 32);
            uint32_t vd = smem_u32 + (2 * KBUF_U + b * VBUF_U) * 16;
            for (int i = tid; i < D_ * 32; i += 256) {
                int d = i >> 5, w_ = i & 31;
                cp16(vd + (d * VROW_U + w_) * 16, gv + i);
            }
            asm volatile("cp.async.commit_group;" ::: "memory");
            asm volatile("cp.async.wait_group 1;" ::: "memory");
        } else {
            asm volatile("cp.async.wait_group 0;" ::: "memory");
        }
        __syncthreads();

        const uint4* Kb = smem4 + (ch & 1) * KBUF_U;
        const uint4* Vb = smem4 + 2 * KBUF_U + (ch & 1) * VBUF_U;

        #pragma unroll
        for (int c4 = 0; c4 < 2; c4++) {
            const int ch64 = ch * 2 + c4;
            float S[8][4];
            #pragma unroll
            for (int nt = 0; nt < 8; nt++) {
                int sk = ch64 + nt + e0;
                S[nt][0] = biasSm[sq0 - sk + 21];
                S[nt][1] = biasSm[sq0 - sk + 20];
                S[nt][2] = biasSm[sq1 - sk + 21];
                S[nt][3] = biasSm[sq1 - sk + 20];
            }
            // --- S += (Q K^T) * scale' (3-pass split bf16), one LDS.128 per frag ---
            #pragma unroll
            for (int nt = 0; nt < 8; nt++) {
                int n = c4 * 64 + nt * 8 + lq;
                #pragma unroll
                for (int ks = 0; ks < 2; ks++) {
                    uint4 w = Kb[n * KROW_U + ks * 4 + le];
                    uint32_t bhh[2] = {w.x, w.y};
                    uint32_t bll[2] = {w.z, w.w};
                    mma_bf16(S[nt], aqh[ks], bhh);
                    mma_bf16(S[nt], aqh[ks], bll);
                    mma_bf16(S[nt], aql[ks], bhh);
                }
            }
            // --- online softmax (log2 domain) ---
            float mx0 = -1e30f, mx1 = -1e30f;
            #pragma unroll
            for (int nt = 0; nt < 8; nt++) {
                mx0 = fmaxf(mx0, fmaxf(S[nt][0], S[nt][1]));
                mx1 = fmaxf(mx1, fmaxf(S[nt][2], S[nt][3]));
            }
            mx0 = fmaxf(mx0, __shfl_xor_sync(0xffffffffu, mx0, 1));
            mx0 = fmaxf(mx0, __shfl_xor_sync(0xffffffffu, mx0, 2));
            mx1 = fmaxf(mx1, __shfl_xor_sync(0xffffffffu, mx1, 1));
            mx1 = fmaxf(mx1, __shfl_xor_sync(0xffffffffu, mx1, 2));
            float mn0 = fmaxf(m0, mx0), mn1 = fmaxf(m1, mx1);
            float al0 = ex2(m0 - mn0), al1 = ex2(m1 - mn1);
            m0 = mn0; m1 = mn1;
            l0 *= al0; l1 *= al1;
            #pragma unroll
            for (int d = 0; d < 4; d++) {
                O[d][0] *= al0; O[d][1] *= al0;
                O[d][2] *= al1; O[d][3] *= al1;
            }
            float ps0 = 0.f, ps1 = 0.f;
            #pragma unroll
            for (int nt = 0; nt < 8; nt++) {
                S[nt][0] = ex2(S[nt][0] - mn0); S[nt][1] = ex2(S[nt][1] - mn0);
                S[nt][2] = ex2(S[nt][2] - mn1); S[nt][3] = ex2(S[nt][3] - mn1);
                ps0 += S[nt][0] + S[nt][1];
                ps1 += S[nt][2] + S[nt][3];
            }
            l0 += ps0; l1 += ps1;
            // --- O += P V (3-pass split bf16) ---
            #pragma unroll
            for (int kk = 0; kk < 4; kk++) {
                uint32_t ah[4], al_[4];
                split2(S[2 * kk][0],     S[2 * kk][1],     ah[0], al_[0]);
                split2(S[2 * kk][2],     S[2 * kk][3],     ah[1], al_[1]);
                split2(S[2 * kk + 1][0], S[2 * kk + 1][1], ah[2], al_[2]);
                split2(S[2 * kk + 1][2], S[2 * kk + 1][3], ah[3], al_[3]);
                int kkloc = c4 * 4 + kk;
                #pragma unroll
                for (int dt = 0; dt < 4; dt++) {
                    uint4 w = Vb[(dt * 8 + lq) * VROW_U + kkloc * 4 + le];
                    uint32_t bhh[2] = {w.x, w.y};
                    uint32_t bll[2] = {w.z, w.w};
                    mma_bf16(O[dt], ah,  bhh);
                    mma_bf16(O[dt], ah,  bll);
                    mma_bf16(O[dt], al_, bhh);
                }
            }
        }
        __syncthreads();
    }

    // --- finalize ---
    l0 += __shfl_xor_sync(0xffffffffu, l0, 1);
    l0 += __shfl_xor_sync(0xffffffffu, l0, 2);
    l1 += __shfl_xor_sync(0xffffffffu, l1, 1);
    l1 += __shfl_xor_sync(0xffffffffu, l1, 2);
    float i0 = 1.f / l0, i1 = 1.f / l1;
    float* ob = out + bhOff;
    #pragma unroll
    for (int dt = 0; dt < 4; dt++) {
        int c = dt * 8 + e0;
        float2 o01; o01.x = O[dt][0] * i0; o01.y = O[dt][1] * i0;
        float2 o23; o23.x = O[dt][2] * i1; o23.y = O[dt][3] * i1;
        *(float2*)(ob + (size_t)r0 * D_ + c) = o01;
        *(float2*)(ob + (size_t)r1 * D_ + c) = o23;
    }
}

// ---------------------------------------------------------------------------
extern "C" void kernel_launch(void* const* d_in, const int* in_sizes, int n_in,
                              void* d_out, int out_size)
{
    const float* q = (const float*)d_in[0];
    const float* k = (const float*)d_in[1];
    const float* v = (const float*)d_in[2];
    int base = (in_sizes[3] == 36) ? 3 : 6;
    const float* pw  = (const float*)d_in[base + 0];
    const float* pb  = (const float*)d_in[base + 1];
    const float* g1  = (const float*)d_in[base + 2];
    const float* b1  = (const float*)d_in[base + 3];
    const float* w1  = (const float*)d_in[base + 4];
    const float* bb1 = (const float*)d_in[base + 5];
    const float* g2  = (const float*)d_in[base + 6];
    const float* b2  = (const float*)d_in[base + 7];
    const float* w2  = (const float*)d_in[base + 8];
    const float* bb2 = (const float*)d_in[base + 9];
    const float* g3  = (const float*)d_in[base + 10];
    const float* b3  = (const float*)d_in[base + 11];
    const float* w3  = (const float*)d_in[base + 12];
    const float* bb3 = (const float*)d_in[base + 13];
    float* out = (float*)d_out;

    cudaFuncSetAttribute(attn_kernel, cudaFuncAttributeMaxDynamicSharedMemorySize, SMEM_BYTES);

    pos_mlp_kernel<<<1, 64>>>(pw, pb, g1, b1, w1, bb1, g2, b2, w2, bb2, g3, b3, w3, bb3);
    split_kv_kernel<<<BH_, 256>>>(k, v);

    dim3 grid(N_ / 128, H_, B_);
    attn_kernel<<<grid, 256, SMEM_BYTES>>>(q, out);
}